// round 3
// baseline (speedup 1.0000x reference)
#include <cuda_runtime.h>
#include <cuda_pipeline.h>

// Correlation / cost-volume layer: kernel_size=1, stride=1, max_disp=4.
// out[b, d, y, x] = (1/C) * sum_c in1[b,c,y,x] * in2[b,c, y+dy-4, x+dx-4]
// d = dy*9 + dx, dy,dx in [0,9). Fixed shapes: B=8, C=192, H=W=128.

#define MAXD 4
#define WIN  9
#define NDISP 81

#define BB 8
#define CC 192
#define HH 128
#define WW 128

#define TH 8            // tile rows per CTA
#define TW 32           // tile cols per CTA
#define KC 6            // channels per chunk (32 chunks)
#define NCHUNK (CC / KC)
#define NTHREADS 160    // 5 dy-groups * (8 ty * 4 tx), 8 px per thread

#define S1SZ (KC * TH * TW)              // 1536 floats per stage
#define S2H  (TH + 8)
#define S2W  (TW + 8)
#define S2SZ (KC * S2H * S2W)            // 3840 floats per stage

// packed f32x2 FMA: d.lo += a.lo*b.lo ; d.hi += a.hi*b.hi
#define FMA2(d, a, b)   asm("fma.rn.f32x2 %0, %1, %2, %0;" : "+l"(d) : "l"(a), "l"(b))
#define PACK2(d, lo, hi) asm("mov.b64 %0, {%1, %2};" : "=l"(d) : "f"(lo), "f"(hi))
#define UNPACK2(lo, hi, v) asm("mov.b64 {%0, %1}, %2;" : "=f"(lo), "=f"(hi) : "l"(v))

__global__ __launch_bounds__(NTHREADS, 2)
void corr_kernel(const float* __restrict__ in1,
                 const float* __restrict__ in2,
                 float* __restrict__ out)
{
    __shared__ float s1[2][KC][TH][TW];          // 12 KB
    __shared__ float s2[2][KC][S2H][S2W];        // 30 KB

    const int tx0 = blockIdx.x * TW;
    const int ty0 = blockIdx.y * TH;
    const int b   = blockIdx.z;

    const int tid   = threadIdx.x;
    const int group = tid >> 5;        // 0..4 ; groups 0-3: dy {2g,2g+1}, group 4: dy 8
    const int lane  = tid & 31;
    const int tx    = lane & 3;        // x-octet index
    const int ty    = lane >> 2;       // 0..7
    const int dy0   = group * 2;

    float* const s1f = &s1[0][0][0][0];
    float* const s2f = &s2[0][0][0][0];

    // ---- chunk-invariant staging descriptors ----
    // s1: 384 16B-chunks per stage -> up to 3 per thread (last partial)
    const float* g1p[3];
    int s1off[3];
    bool s1v[3];
    #pragma unroll
    for (int t = 0; t < 3; ++t) {
        int idx = tid + t * NTHREADS;
        s1v[t] = (idx < S1SZ / 4);
        int cidx = s1v[t] ? idx : 0;
        int kc  = cidx >> 6;           // / (8 rows * 8 quads)
        int rem = cidx & 63;
        int r   = rem >> 3;
        int c4  = rem & 7;
        s1off[t] = (kc * TH + r) * TW + c4 * 4;
        g1p[t]   = in1 + (((long)(b * CC + kc) * HH + (ty0 + r)) * WW + tx0 + c4 * 4);
    }
    // s2: 960 16B-chunks per stage -> exactly 6 per thread; all-or-nothing zfill
    const float* g2p[6];
    int s2off[6];
    unsigned zfill[6];
    #pragma unroll
    for (int t = 0; t < 6; ++t) {
        int idx = tid + t * NTHREADS;
        int kc  = idx / 160;
        int rem = idx % 160;
        int r   = rem / 10;
        int c   = rem % 10;
        int gy  = ty0 + r - MAXD;
        int gx  = tx0 + c * 4 - MAXD;
        bool valid = (gy >= 0) && (gy < HH) && (gx >= 0) && (gx <= WW - 4);
        zfill[t] = valid ? 0u : 16u;
        int cgy = min(max(gy, 0), HH - 1);
        int cgx = min(max(gx, 0), WW - 4);
        s2off[t] = (kc * S2H + r) * S2W + c * 4;
        g2p[t]   = in2 + (((long)(b * CC + kc) * HH + cgy) * WW + cgx);
    }

    // ---- accumulators: [row-in-group][dx][px-pair], f32x2 packed ----
    unsigned long long acc2[2][WIN][4];
    #pragma unroll
    for (int r = 0; r < 2; ++r)
        #pragma unroll
        for (int dx = 0; dx < WIN; ++dx)
            #pragma unroll
            for (int pp = 0; pp < 4; ++pp)
                acc2[r][dx][pp] = 0ull;

    const long CHUNK_STRIDE = (long)KC * HH * WW;

    // prologue: stage chunk 0 into buf 0
    #pragma unroll
    for (int t = 0; t < 3; ++t)
        if (s1v[t]) __pipeline_memcpy_async(s1f + s1off[t], g1p[t], 16);
    #pragma unroll
    for (int t = 0; t < 6; ++t)
        __pipeline_memcpy_async(s2f + s2off[t], g2p[t], 16, zfill[t]);
    __pipeline_commit();

    #pragma unroll 2
    for (int k = 0; k < NCHUNK; ++k) {
        const int buf = k & 1;
        if (k + 1 < NCHUNK) {
            const long coff = (long)(k + 1) * CHUNK_STRIDE;
            const int nb = buf ^ 1;
            #pragma unroll
            for (int t = 0; t < 3; ++t)
                if (s1v[t]) __pipeline_memcpy_async(s1f + nb * S1SZ + s1off[t], g1p[t] + coff, 16);
            #pragma unroll
            for (int t = 0; t < 6; ++t)
                __pipeline_memcpy_async(s2f + nb * S2SZ + s2off[t], g2p[t] + coff, 16, zfill[t]);
            __pipeline_commit();
            __pipeline_wait_prior(1);
        } else {
            __pipeline_wait_prior(0);
        }
        __syncthreads();

        // ---- compute chunk k ----
        #pragma unroll
        for (int kc = 0; kc < KC; ++kc) {
            const float* arow = &s1[buf][kc][ty][tx * 8];
            float4 a0 = *(const float4*)arow;
            float4 a1 = *(const float4*)(arow + 4);
            unsigned long long aP[4];
            PACK2(aP[0], a0.x, a0.y);
            PACK2(aP[1], a0.z, a0.w);
            PACK2(aP[2], a1.x, a1.y);
            PACK2(aP[3], a1.z, a1.w);

            #pragma unroll
            for (int r = 0; r < 2; ++r) {
                if (r == 1 && group == 4) break;   // group 4 owns only dy=8
                const float* rowp = &s2[buf][kc][ty + dy0 + r][tx * 8];
                float4 q0 = *(const float4*)(rowp);
                float4 q1 = *(const float4*)(rowp + 4);
                float4 q2 = *(const float4*)(rowp + 8);
                float4 q3 = *(const float4*)(rowp + 12);
                float rf[16] = {q0.x, q0.y, q0.z, q0.w,
                                q1.x, q1.y, q1.z, q1.w,
                                q2.x, q2.y, q2.z, q2.w,
                                q3.x, q3.y, q3.z, q3.w};
                unsigned long long e[8], o[7];
                #pragma unroll
                for (int i = 0; i < 8; ++i)
                    PACK2(e[i], rf[2 * i], rf[2 * i + 1]);      // elided by ptxas (aligned quads)
                #pragma unroll
                for (int i = 0; i < 7; ++i)
                    PACK2(o[i], rf[2 * i + 1], rf[2 * i + 2]);  // genuine repack

                #pragma unroll
                for (int dx = 0; dx < WIN; ++dx) {
                    #pragma unroll
                    for (int pp = 0; pp < 4; ++pp) {
                        const int off = dx + 2 * pp;
                        if (off & 1)
                            FMA2(acc2[r][dx][pp], aP[pp], o[off >> 1]);
                        else
                            FMA2(acc2[r][dx][pp], aP[pp], e[off >> 1]);
                    }
                }
            }
        }
        __syncthreads();
    }

    // ---- epilogue: scale by 1/C, two float4 stores per (row,dx) ----
    const float scale = 1.0f / (float)CC;
    const int y  = ty0 + ty;
    const int x0 = tx0 + tx * 8;
    const int nrow = (group < 4) ? 2 : 1;
    for (int r = 0; r < nrow; ++r) {
        #pragma unroll
        for (int dx = 0; dx < WIN; ++dx) {
            int d = (dy0 + r) * WIN + dx;
            float f0, f1, f2, f3, f4, f5, f6, f7;
            UNPACK2(f0, f1, acc2[r][dx][0]);
            UNPACK2(f2, f3, acc2[r][dx][1]);
            UNPACK2(f4, f5, acc2[r][dx][2]);
            UNPACK2(f6, f7, acc2[r][dx][3]);
            float* op = &out[(((long)(b * NDISP) + d) * HH + y) * WW + x0];
            *(float4*)op       = make_float4(f0 * scale, f1 * scale, f2 * scale, f3 * scale);
            *(float4*)(op + 4) = make_float4(f4 * scale, f5 * scale, f6 * scale, f7 * scale);
        }
    }
}

extern "C" void kernel_launch(void* const* d_in, const int* in_sizes, int n_in,
                              void* d_out, int out_size)
{
    const float* in1 = (const float*)d_in[0];
    const float* in2 = (const float*)d_in[1];
    float* out = (float*)d_out;

    dim3 grid(WW / TW, HH / TH, BB);   // (4, 16, 8) = 512 CTAs
    dim3 block(NTHREADS);
    corr_kernel<<<grid, block>>>(in1, in2, out);
}

// round 4
// speedup vs baseline: 2.3831x; 2.3831x over previous
#include <cuda_runtime.h>
#include <cuda.h>

// Correlation / cost-volume layer: kernel_size=1, stride=1, max_disp=4.
// out[b, d, y, x] = (1/C) * sum_c in1[b,c,y,x] * in2[b,c, y+dy-4, x+dx-4]
// d = dy*9 + dx, dy,dx in [0,9). Fixed shapes: B=8, C=192, H=W=128.

#define MAXD 4
#define WIN  9
#define NDISP 81

#define BB 8
#define CC 192
#define HH 128
#define WW 128

#define TH 8            // tile rows per CTA
#define TW 32           // tile cols per CTA
#define KC 6            // channels per chunk (32 chunks)
#define NCHUNK (CC / KC)
#define NTHREADS 192    // 3 dy-groups * (8 ty * 8 tx)

#define S2H  (TH + 8)
#define S2W  (TW + 8)
#define S1BYTES (KC * TH * TW * 4)       // 6144
#define S2BYTES (KC * S2H * S2W * 4)     // 15360
#define CHUNK_BYTES (S1BYTES + S2BYTES)  // 21504

// packed f32x2 ops
#define FMA2(d, a, b)      asm("fma.rn.f32x2 %0, %1, %2, %0;" : "+l"(d) : "l"(a), "l"(b))
#define PACK2(d, lo, hi)   asm("mov.b64 %0, {%1, %2};" : "=l"(d) : "f"(lo), "f"(hi))
#define UNPACK2(lo, hi, v) asm("mov.b64 {%0, %1}, %2;" : "=f"(lo), "=f"(hi) : "l"(v))

__device__ __forceinline__ unsigned smem_u32(const void* p) {
    unsigned a;
    asm("{ .reg .u64 t; cvta.to.shared.u64 t, %1; cvt.u32.u64 %0, t; }"
        : "=r"(a) : "l"(p));
    return a;
}

__device__ __forceinline__ void mbar_init(unsigned mbar, unsigned count) {
    asm volatile("mbarrier.init.shared.b64 [%0], %1;" :: "r"(mbar), "r"(count) : "memory");
}
__device__ __forceinline__ void mbar_expect_tx(unsigned mbar, unsigned bytes) {
    asm volatile("mbarrier.arrive.expect_tx.shared.b64 _, [%0], %1;"
                 :: "r"(mbar), "r"(bytes) : "memory");
}
__device__ __forceinline__ void mbar_wait(unsigned mbar, unsigned parity) {
    asm volatile(
        "{\n\t"
        ".reg .pred P;\n\t"
        "WAIT_LOOP_%=:\n\t"
        "mbarrier.try_wait.parity.acquire.cta.shared::cta.b64 P, [%0], %1, 0x989680;\n\t"
        "@P bra.uni WAIT_DONE_%=;\n\t"
        "bra.uni WAIT_LOOP_%=;\n\t"
        "WAIT_DONE_%=:\n\t"
        "}"
        :: "r"(mbar), "r"(parity) : "memory");
}
__device__ __forceinline__ void tma_load_3d(unsigned smem_dst, const void* tmap,
                                            int cx, int cy, int cz, unsigned mbar) {
    asm volatile(
        "cp.async.bulk.tensor.3d.shared::cta.global.tile.mbarrier::complete_tx::bytes "
        "[%0], [%1, {%2, %3, %4}], [%5];"
        :: "r"(smem_dst), "l"(tmap), "r"(cx), "r"(cy), "r"(cz), "r"(mbar)
        : "memory");
}

__global__ __launch_bounds__(NTHREADS, 2)
void corr_kernel(const __grid_constant__ CUtensorMap t1map,
                 const __grid_constant__ CUtensorMap t2map,
                 float* __restrict__ out)
{
    __shared__ __align__(128) float s1[2][KC][TH][TW];      // 12 KB
    __shared__ __align__(128) float s2[2][KC][S2H][S2W];    // 30 KB
    __shared__ __align__(8) unsigned long long mbar_full[2];

    const int tx0 = blockIdx.x * TW;
    const int ty0 = blockIdx.y * TH;
    const int b   = blockIdx.z;

    const int tid   = threadIdx.x;
    const int group = tid / 64;        // dy group: dy in [3g, 3g+3)
    const int ptid  = tid % 64;
    const int tx    = ptid % 8;        // x-quad index
    const int ty    = ptid / 8;        // 0..7
    const int dyb   = group * 3;

    const unsigned mb0 = smem_u32(&mbar_full[0]);
    const unsigned mb1 = smem_u32(&mbar_full[1]);
    const unsigned s1a[2] = { smem_u32(&s1[0][0][0][0]), smem_u32(&s1[1][0][0][0]) };
    const unsigned s2a[2] = { smem_u32(&s2[0][0][0][0]), smem_u32(&s2[1][0][0][0]) };
    const int zbase = b * CC;

    if (tid == 0) { mbar_init(mb0, 1); mbar_init(mb1, 1); }
    __syncthreads();

    if (tid == 0) {
        // prologue: chunk 0 -> buf 0, chunk 1 -> buf 1
        mbar_expect_tx(mb0, CHUNK_BYTES);
        tma_load_3d(s1a[0], &t1map, tx0, ty0, zbase, mb0);
        tma_load_3d(s2a[0], &t2map, tx0 - MAXD, ty0 - MAXD, zbase, mb0);
        mbar_expect_tx(mb1, CHUNK_BYTES);
        tma_load_3d(s1a[1], &t1map, tx0, ty0, zbase + KC, mb1);
        tma_load_3d(s2a[1], &t2map, tx0 - MAXD, ty0 - MAXD, zbase + KC, mb1);
    }

    // accumulators: [g-row][dx][px-pair], f32x2 packed (108 regs)
    unsigned long long acc2[3][WIN][2];
    #pragma unroll
    for (int g = 0; g < 3; ++g)
        #pragma unroll
        for (int dx = 0; dx < WIN; ++dx)
            #pragma unroll
            for (int pp = 0; pp < 2; ++pp)
                acc2[g][dx][pp] = 0ull;

    #pragma unroll 2
    for (int k = 0; k < NCHUNK; ++k) {
        const int buf = k & 1;
        const unsigned par = (unsigned)((k >> 1) & 1);
        mbar_wait(buf ? mb1 : mb0, par);

        // ---- compute chunk k from buf ----
        #pragma unroll
        for (int kc = 0; kc < KC; ++kc) {
            float4 a4 = *(const float4*)&s1[buf][kc][ty][tx * 4];
            unsigned long long aP[2];
            PACK2(aP[0], a4.x, a4.y);
            PACK2(aP[1], a4.z, a4.w);

            #pragma unroll
            for (int g = 0; g < 3; ++g) {
                const float* rowp = &s2[buf][kc][ty + dyb + g][tx * 4];
                float4 q0 = *(const float4*)(rowp);
                float4 q1 = *(const float4*)(rowp + 4);
                float4 q2 = *(const float4*)(rowp + 8);
                // even pairs alias the loaded quads (elided by ptxas)
                unsigned long long e[6];
                PACK2(e[0], q0.x, q0.y); PACK2(e[1], q0.z, q0.w);
                PACK2(e[2], q1.x, q1.y); PACK2(e[3], q1.z, q1.w);
                PACK2(e[4], q2.x, q2.y); PACK2(e[5], q2.z, q2.w);
                // odd pairs: genuine repacks
                unsigned long long o[5];
                PACK2(o[0], q0.y, q0.z); PACK2(o[1], q0.w, q1.x);
                PACK2(o[2], q1.y, q1.z); PACK2(o[3], q1.w, q2.x);
                PACK2(o[4], q2.y, q2.z);

                #pragma unroll
                for (int dx = 0; dx < WIN; ++dx) {
                    #pragma unroll
                    for (int pp = 0; pp < 2; ++pp) {
                        const int off = dx + 2 * pp;
                        if (off & 1)
                            FMA2(acc2[g][dx][pp], aP[pp], o[off >> 1]);
                        else
                            FMA2(acc2[g][dx][pp], aP[pp], e[off >> 1]);
                    }
                }
            }
        }
        __syncthreads();

        // refill this buffer with chunk k+2
        if (k + 2 < NCHUNK && tid == 0) {
            const unsigned mb = buf ? mb1 : mb0;
            mbar_expect_tx(mb, CHUNK_BYTES);
            tma_load_3d(s1a[buf], &t1map, tx0, ty0, zbase + (k + 2) * KC, mb);
            tma_load_3d(s2a[buf], &t2map, tx0 - MAXD, ty0 - MAXD, zbase + (k + 2) * KC, mb);
        }
    }

    // ---- epilogue: scale by 1/C, float4 stores, coalesced ----
    const float scale = 1.0f / (float)CC;
    const int y  = ty0 + ty;
    const int x0 = tx0 + tx * 4;
    #pragma unroll
    for (int g = 0; g < 3; ++g) {
        #pragma unroll
        for (int dx = 0; dx < WIN; ++dx) {
            int d = (dyb + g) * WIN + dx;
            float f0, f1, f2, f3;
            UNPACK2(f0, f1, acc2[g][dx][0]);
            UNPACK2(f2, f3, acc2[g][dx][1]);
            *(float4*)&out[(((long)(b * NDISP) + d) * HH + y) * WW + x0] =
                make_float4(f0 * scale, f1 * scale, f2 * scale, f3 * scale);
        }
    }
}

typedef CUresult (*EncodeFn)(CUtensorMap*, CUtensorMapDataType, cuuint32_t, void*,
                             const cuuint64_t*, const cuuint64_t*, const cuuint32_t*,
                             const cuuint32_t*, CUtensorMapInterleave, CUtensorMapSwizzle,
                             CUtensorMapL2promotion, CUtensorMapFloatOOBfill);

extern "C" void kernel_launch(void* const* d_in, const int* in_sizes, int n_in,
                              void* d_out, int out_size)
{
    float* in1 = (float*)d_in[0];
    float* in2 = (float*)d_in[1];
    float* out = (float*)d_out;

    EncodeFn encode = nullptr;
    cudaDriverEntryPointQueryResult qr;
    cudaGetDriverEntryPoint("cuTensorMapEncodeTiled", (void**)&encode,
                            cudaEnableDefault, &qr);

    CUtensorMap t1map, t2map;
    cuuint64_t dims[3]    = { WW, HH, (cuuint64_t)(BB * CC) };
    cuuint64_t strides[2] = { WW * 4ull, (cuuint64_t)HH * WW * 4ull };
    cuuint32_t elemstr[3] = { 1, 1, 1 };

    cuuint32_t box1[3] = { TW, TH, KC };
    encode(&t1map, CU_TENSOR_MAP_DATA_TYPE_FLOAT32, 3, in1,
           dims, strides, box1, elemstr,
           CU_TENSOR_MAP_INTERLEAVE_NONE, CU_TENSOR_MAP_SWIZZLE_NONE,
           CU_TENSOR_MAP_L2_PROMOTION_L2_128B, CU_TENSOR_MAP_FLOAT_OOB_FILL_NONE);

    cuuint32_t box2[3] = { S2W, S2H, KC };
    encode(&t2map, CU_TENSOR_MAP_DATA_TYPE_FLOAT32, 3, in2,
           dims, strides, box2, elemstr,
           CU_TENSOR_MAP_INTERLEAVE_NONE, CU_TENSOR_MAP_SWIZZLE_NONE,
           CU_TENSOR_MAP_L2_PROMOTION_L2_128B, CU_TENSOR_MAP_FLOAT_OOB_FILL_NONE);

    dim3 grid(WW / TW, HH / TH, BB);   // (4, 16, 8) = 512 CTAs
    dim3 block(NTHREADS);
    corr_kernel<<<grid, block>>>(t1map, t2map, out);
}